// round 4
// baseline (speedup 1.0000x reference)
#include <cuda_runtime.h>
#include <cuda_bf16.h>

// Sinkhorn OT loss, B=1024, N=M=256, 100 iters. One CTA per batch.
// K = exp(-C/eps) as bf16 in smem, rows padded to 129 words (conflict-free
// for column access AND for the one-time per-thread row fetch).
// Row matvec (K v) runs entirely from registers (thread t holds row t).
// Column matvec (K^T u) reads K from smem. All FMAs are packed f32x2.

#define B_TOT   1024
#define ITERS   100
#define INV_EPS 10.0f
#define EPS_DIV 1e-8f

#define ROWW 258                       // bf16 per padded row = 129 words
#define SMEM_BYTES (256*ROWW*2 /*K*/ + 4*256*4 /*a,b,u,v*/ + 512*4 /*psum*/)

__device__ float g_cost[B_TOT];

__device__ __forceinline__ float bflo(unsigned int p) { return __uint_as_float(p << 16); }
__device__ __forceinline__ float bfhi(unsigned int p) { return __uint_as_float(p & 0xffff0000u); }

// ---- packed f32x2 helpers (Blackwell base ISA, sm_100+) ----
__device__ __forceinline__ unsigned long long pk(unsigned int lo, unsigned int hi) {
    unsigned long long r;
    asm("mov.b64 %0, {%1, %2};" : "=l"(r) : "r"(lo), "r"(hi));
    return r;
}
__device__ __forceinline__ unsigned long long pkf(float lo, float hi) {
    unsigned long long r;
    asm("mov.b64 %0, {%1, %2};" : "=l"(r) : "f"(lo), "f"(hi));
    return r;
}
__device__ __forceinline__ void fma2(unsigned long long& d,
                                     unsigned long long a, unsigned long long b) {
    asm("fma.rn.f32x2 %0, %1, %2, %0;" : "+l"(d) : "l"(a), "l"(b));
}
__device__ __forceinline__ float hsum2(unsigned long long p) {
    float lo, hi;
    asm("mov.b64 {%0, %1}, %2;" : "=f"(lo), "=f"(hi) : "l"(p));
    return lo + hi;
}

extern __shared__ unsigned char smem_raw[];

__global__ __launch_bounds__(256, 1)
void sinkhorn_kernel(const float* __restrict__ C,
                     const float* __restrict__ mass_pred,
                     const float* __restrict__ mass_target)
{
    unsigned short* sK = (unsigned short*)smem_raw;           // 256 x 258 bf16
    float* s_u  = (float*)(smem_raw + 256 * ROWW * 2);        // 256
    float* s_v  = s_u + 256;                                  // 256
    float* s_a  = s_v + 256;                                  // 256
    float* s_b  = s_a + 256;                                  // 256
    float* s_ps = s_b + 256;                                  // 512 partials

    const int b = blockIdx.x;
    const int t = threadIdx.x;
    const float* __restrict__ Cb = C + (size_t)b * 65536;
    const unsigned int* sKw = (const unsigned int*)sK;

    // ---------- Build K = exp(-C/eps) into smem (bf16, padded rows) ----------
    #pragma unroll 4
    for (int k = 0; k < 64; k++) {
        int idx4 = k * 256 + t;                 // coalesced float4 index
        float4 c = ((const float4*)Cb)[idx4];
        int lin = idx4 * 4;
        int n = lin >> 8;
        int m = lin & 255;
        __nv_bfloat162 p0 = __floats2bfloat162_rn(__expf(-c.x * INV_EPS),
                                                  __expf(-c.y * INV_EPS));
        __nv_bfloat162 p1 = __floats2bfloat162_rn(__expf(-c.z * INV_EPS),
                                                  __expf(-c.w * INV_EPS));
        *(__nv_bfloat162*)&sK[n * ROWW + m]     = p0;
        *(__nv_bfloat162*)&sK[n * ROWW + m + 2] = p1;
    }

    // ---------- Normalize masses ----------
    float mpv = mass_pred[b * 256 + t];
    float mtv = mass_target[b * 256 + t];
    float sa = mpv, sb = mtv;
    #pragma unroll
    for (int o = 16; o; o >>= 1) {
        sa += __shfl_xor_sync(0xffffffffu, sa, o);
        sb += __shfl_xor_sync(0xffffffffu, sb, o);
    }
    if ((t & 31) == 0) { s_ps[t >> 5] = sa; s_ps[8 + (t >> 5)] = sb; }
    __syncthreads();
    float suma = 0.f, sumb = 0.f;
    #pragma unroll
    for (int w = 0; w < 8; w++) { suma += s_ps[w]; sumb += s_ps[8 + w]; }
    s_a[t] = mpv / (suma + EPS_DIV);
    s_b[t] = mtv / (sumb + EPS_DIV);
    s_u[t] = 1.0f;
    __syncthreads();

    // ---------- Preload own K row into registers (conflict-free: 129-word rows) ----------
    unsigned int kreg[128];
    #pragma unroll
    for (int i = 0; i < 128; i++) kreg[i] = sKw[t * 129 + i];

    // ---------- 100 Sinkhorn iterations ----------
    const int j  = t & 127;    // column-pair index: owns columns (2j, 2j+1)
    const int h  = t >> 7;     // n-half: rows [128h, 128h+128)
    const int n0 = h << 7;

    for (int it = 0; it < ITERS; it++) {
        // step 1: Kt_u[m] = sum_n K[n][m] * u[n]   (column access from smem)
        unsigned long long accA = 0ull, accB = 0ull;   // (lo-col) and (hi-col) sums
        unsigned long long accA2 = 0ull, accB2 = 0ull;
        #pragma unroll 8
        for (int nn = 0; nn < 128; nn += 4) {
            float4 uu = *(const float4*)&s_u[n0 + nn];
            unsigned int p0 = sKw[(n0 + nn)     * 129 + j];
            unsigned int p1 = sKw[(n0 + nn + 1) * 129 + j];
            unsigned int p2 = sKw[(n0 + nn + 2) * 129 + j];
            unsigned int p3 = sKw[(n0 + nn + 3) * 129 + j];
            unsigned long long u01 = pkf(uu.x, uu.y);
            unsigned long long u23 = pkf(uu.z, uu.w);
            fma2(accA,  pk(p0 << 16,          p1 << 16),          u01);
            fma2(accB,  pk(p0 & 0xffff0000u,  p1 & 0xffff0000u),  u01);
            fma2(accA2, pk(p2 << 16,          p3 << 16),          u23);
            fma2(accB2, pk(p2 & 0xffff0000u,  p3 & 0xffff0000u),  u23);
        }
        float a0 = hsum2(accA) + hsum2(accA2);
        float a1 = hsum2(accB) + hsum2(accB2);
        *(float2*)&s_ps[(h << 8) + (j << 1)] = make_float2(a0, a1);
        __syncthreads();

        float kt = s_ps[t] + s_ps[256 + t];
        s_v[t] = __fdividef(s_b[t], kt + EPS_DIV);
        __syncthreads();

        // step 2: K_v[n] = sum_m K[n][m] * v[m]   (row from registers)
        unsigned long long acc0 = 0ull, acc1 = 0ull;
        #pragma unroll
        for (int i = 0; i < 128; i += 2) {
            float4 vv = *(const float4*)&s_v[i * 2];
            unsigned int w0 = kreg[i];
            unsigned int w1 = kreg[i + 1];
            fma2(acc0, pk(w0 << 16, w0 & 0xffff0000u), pkf(vv.x, vv.y));
            fma2(acc1, pk(w1 << 16, w1 & 0xffff0000u), pkf(vv.z, vv.w));
        }
        float kv = hsum2(acc0) + hsum2(acc1);
        s_u[t] = __fdividef(s_a[t], kv + EPS_DIV);
        __syncthreads();
    }

    // ---------- ot_cost[b] = sum_{n,m} u[n] * K[n,m] * v[m] * C[n,m] ----------
    float acc = 0.f;
    #pragma unroll 4
    for (int k = 0; k < 64; k++) {
        int idx4 = k * 256 + t;
        float4 c = ((const float4*)Cb)[idx4];
        int lin = idx4 * 4;
        int n = lin >> 8;
        int m = lin & 255;
        unsigned int q0 = sKw[n * 129 + (m >> 1)];
        unsigned int q1 = sKw[n * 129 + (m >> 1) + 1];
        float un = s_u[n];
        float4 vv = *(const float4*)&s_v[m];
        acc += un * (bflo(q0) * vv.x * c.x + bfhi(q0) * vv.y * c.y
                   + bflo(q1) * vv.z * c.z + bfhi(q1) * vv.w * c.w);
    }
    #pragma unroll
    for (int o = 16; o; o >>= 1) acc += __shfl_xor_sync(0xffffffffu, acc, o);
    __syncthreads();
    if ((t & 31) == 0) s_ps[t >> 5] = acc;
    __syncthreads();
    if (t == 0) {
        float s = 0.f;
        #pragma unroll
        for (int w = 0; w < 8; w++) s += s_ps[w];
        g_cost[b] = s;
    }
}

__global__ void reduce_kernel(float* __restrict__ out)
{
    __shared__ float sm[8];
    int t = threadIdx.x;
    float s = 0.f;
    #pragma unroll
    for (int i = t; i < B_TOT; i += 256) s += g_cost[i];
    #pragma unroll
    for (int o = 16; o; o >>= 1) s += __shfl_xor_sync(0xffffffffu, s, o);
    if ((t & 31) == 0) sm[t >> 5] = s;
    __syncthreads();
    if (t == 0) {
        float tot = 0.f;
        #pragma unroll
        for (int w = 0; w < 8; w++) tot += sm[w];
        out[0] = tot * (1.0f / B_TOT);
    }
}

extern "C" void kernel_launch(void* const* d_in, const int* in_sizes, int n_in,
                              void* d_out, int out_size)
{
    const float* C  = (const float*)d_in[0];
    const float* mp = (const float*)d_in[1];
    const float* mt = (const float*)d_in[2];
    float* out = (float*)d_out;

    cudaFuncSetAttribute(sinkhorn_kernel,
                         cudaFuncAttributeMaxDynamicSharedMemorySize, SMEM_BYTES);

    sinkhorn_kernel<<<B_TOT, 256, SMEM_BYTES>>>(C, mp, mt);
    reduce_kernel<<<1, 256>>>(out);
}

// round 5
// speedup vs baseline: 1.3055x; 1.3055x over previous
#include <cuda_runtime.h>
#include <cuda_bf16.h>

// Sinkhorn OT loss, B=1024, N=M=256, 100 iters. One CTA (512 threads) per batch.
// K = exp(-C/eps) bf16 in smem, rows padded to 132 words (528B, 16B aligned).
// BOTH matvecs read K row-major via LDS.128 (conflict-free):
//   K^T u: lane owns 8 columns; 16-row groups produce partials, reduced in smem.
//   K v:   thread owns (row, column-half); pair-combined in smem.

#define B_TOT   1024
#define ITERS   100
#define INV_EPS 10.0f
#define EPS_DIV 1e-8f

#define ROWW_W  132                        // words per padded K row
#define OFF_A   (256*ROWW_W*4)             // 135168
#define OFF_B   (OFF_A + 1024)
#define OFF_U   (OFF_B + 1024)
#define OFF_V   (OFF_U + 1024)
#define OFF_PS  (OFF_V + 1024)             // 16*256 floats = 16KB
#define SMEM_BYTES (OFF_PS + 16*256*4)     // 155648

__device__ float g_cost[B_TOT];

__device__ __forceinline__ float bflo(unsigned int p) { return __uint_as_float(p << 16); }
__device__ __forceinline__ float bfhi(unsigned int p) { return __uint_as_float(p & 0xffff0000u); }

extern __shared__ unsigned char smem_raw[];

__global__ __launch_bounds__(512, 1)
void sinkhorn_kernel(const float* __restrict__ C,
                     const float* __restrict__ mass_pred,
                     const float* __restrict__ mass_target)
{
    unsigned short* sK = (unsigned short*)smem_raw;            // 256 x 264 bf16
    const unsigned int* sKw = (const unsigned int*)smem_raw;   // word view
    float* s_a  = (float*)(smem_raw + OFF_A);
    float* s_b  = (float*)(smem_raw + OFF_B);
    float* s_u  = (float*)(smem_raw + OFF_U);
    float* s_v  = (float*)(smem_raw + OFF_V);
    float* s_ps = (float*)(smem_raw + OFF_PS);

    const int b = blockIdx.x;
    const int t = threadIdx.x;
    const float* __restrict__ Cb = C + (size_t)b * 65536;

    // ---------- Build K = exp(-C/eps) (bf16, padded rows) ----------
    #pragma unroll 4
    for (int k = 0; k < 32; k++) {
        int idx4 = k * 512 + t;                // coalesced float4 index
        float4 c = ((const float4*)Cb)[idx4];
        int lin = idx4 << 2;
        int n = lin >> 8;
        int m = lin & 255;
        __nv_bfloat162 p0 = __floats2bfloat162_rn(__expf(-c.x * INV_EPS),
                                                  __expf(-c.y * INV_EPS));
        __nv_bfloat162 p1 = __floats2bfloat162_rn(__expf(-c.z * INV_EPS),
                                                  __expf(-c.w * INV_EPS));
        *(__nv_bfloat162*)&sK[n * (ROWW_W*2) + m]     = p0;
        *(__nv_bfloat162*)&sK[n * (ROWW_W*2) + m + 2] = p1;
    }

    // ---------- Normalize masses (threads 0-255) ----------
    if (t < 256) {
        float mpv = mass_pred[b * 256 + t];
        float mtv = mass_target[b * 256 + t];
        float sa = mpv, sb = mtv;
        #pragma unroll
        for (int o = 16; o; o >>= 1) {
            sa += __shfl_xor_sync(0xffffffffu, sa, o);
            sb += __shfl_xor_sync(0xffffffffu, sb, o);
        }
        if ((t & 31) == 0) { s_ps[t >> 5] = sa; s_ps[8 + (t >> 5)] = sb; }
        s_ps[64 + t] = mpv;            // stash raw values
        s_ps[320 + t] = mtv;
    }
    __syncthreads();
    if (t < 256) {
        float suma = 0.f, sumb = 0.f;
        #pragma unroll
        for (int w = 0; w < 8; w++) { suma += s_ps[w]; sumb += s_ps[8 + w]; }
        s_a[t] = s_ps[64 + t]  / (suma + EPS_DIV);
        s_b[t] = s_ps[320 + t] / (sumb + EPS_DIV);
        s_u[t] = 1.0f;
    }
    __syncthreads();

    // ---------- Iteration index maps ----------
    const int g  = t >> 5;        // row-group 0..15 (16 rows each)      [loop1]
    const int l  = t & 31;        // lane: owns columns 8l..8l+7         [loop1]
    const int n0 = g << 4;
    const int nr = t & 255;       // row                                  [loop2]
    const int hh = t >> 8;        // column half                          [loop2]

    for (int it = 0; it < ITERS; it++) {
        // ===== step 1: Kt_u[m] = sum_n K[n][m]*u[n]  (row-major loads) =====
        float a0=0.f,a1=0.f,a2=0.f,a3=0.f,a4=0.f,a5=0.f,a6=0.f,a7=0.f;
        #pragma unroll
        for (int r4 = 0; r4 < 4; r4++) {
            float4 uu = *(const float4*)&s_u[n0 + (r4 << 2)];
            #pragma unroll
            for (int r = 0; r < 4; r++) {
                uint4 kw = *(const uint4*)&sKw[(n0 + (r4 << 2) + r) * ROWW_W + (l << 2)];
                float ur = (r == 0) ? uu.x : (r == 1) ? uu.y : (r == 2) ? uu.z : uu.w;
                a0 += bflo(kw.x) * ur;  a1 += bfhi(kw.x) * ur;
                a2 += bflo(kw.y) * ur;  a3 += bfhi(kw.y) * ur;
                a4 += bflo(kw.z) * ur;  a5 += bfhi(kw.z) * ur;
                a6 += bflo(kw.w) * ur;  a7 += bfhi(kw.w) * ur;
            }
        }
        *(float4*)&s_ps[g * 256 + (l << 3)]     = make_float4(a0, a1, a2, a3);
        *(float4*)&s_ps[g * 256 + (l << 3) + 4] = make_float4(a4, a5, a6, a7);
        __syncthreads();

        if (t < 256) {
            float kt = 0.f;
            #pragma unroll
            for (int gg = 0; gg < 16; gg++) kt += s_ps[gg * 256 + t];
            s_v[t] = __fdividef(s_b[t], kt + EPS_DIV);
        }
        __syncthreads();

        // ===== step 2: K_v[n] = sum_m K[n][m]*v[m]  (row, column-half) =====
        float c0 = 0.f, c1 = 0.f;
        #pragma unroll
        for (int w = 0; w < 16; w++) {
            uint4 kw = *(const uint4*)&sKw[nr * ROWW_W + (hh << 6) + (w << 2)];
            float4 v0 = *(const float4*)&s_v[(hh << 7) + (w << 3)];
            float4 v1 = *(const float4*)&s_v[(hh << 7) + (w << 3) + 4];
            c0 += bflo(kw.x) * v0.x + bfhi(kw.x) * v0.y;
            c1 += bflo(kw.y) * v0.z + bfhi(kw.y) * v0.w;
            c0 += bflo(kw.z) * v1.x + bfhi(kw.z) * v1.y;
            c1 += bflo(kw.w) * v1.z + bfhi(kw.w) * v1.w;
        }
        s_ps[(hh << 8) + nr] = c0 + c1;
        __syncthreads();

        if (t < 256) {
            float kv = s_ps[t] + s_ps[256 + t];
            s_u[t] = __fdividef(s_a[t], kv + EPS_DIV);
        }
        __syncthreads();
    }

    // ---------- ot_cost[b] = sum u[n] K[n,m] v[m] C[n,m] ----------
    float acc = 0.f;
    #pragma unroll 4
    for (int k = 0; k < 32; k++) {
        int idx4 = k * 512 + t;
        float4 c = ((const float4*)Cb)[idx4];
        int lin = idx4 << 2;
        int n = lin >> 8;
        int m = lin & 255;
        uint2 q = *(const uint2*)&sKw[n * ROWW_W + (m >> 1)];
        float un = s_u[n];
        float4 vv = *(const float4*)&s_v[m];
        acc += un * (bflo(q.x) * vv.x * c.x + bfhi(q.x) * vv.y * c.y
                   + bflo(q.y) * vv.z * c.z + bfhi(q.y) * vv.w * c.w);
    }
    #pragma unroll
    for (int o = 16; o; o >>= 1) acc += __shfl_xor_sync(0xffffffffu, acc, o);
    __syncthreads();
    if ((t & 31) == 0) s_ps[t >> 5] = acc;
    __syncthreads();
    if (t == 0) {
        float s = 0.f;
        #pragma unroll
        for (int w = 0; w < 16; w++) s += s_ps[w];
        g_cost[b] = s;
    }
}

__global__ void reduce_kernel(float* __restrict__ out)
{
    __shared__ float sm[8];
    int t = threadIdx.x;
    float s = 0.f;
    #pragma unroll
    for (int i = t; i < B_TOT; i += 256) s += g_cost[i];
    #pragma unroll
    for (int o = 16; o; o >>= 1) s += __shfl_xor_sync(0xffffffffu, s, o);
    if ((t & 31) == 0) sm[t >> 5] = s;
    __syncthreads();
    if (t == 0) {
        float tot = 0.f;
        #pragma unroll
        for (int w = 0; w < 8; w++) tot += sm[w];
        out[0] = tot * (1.0f / B_TOT);
    }
}

extern "C" void kernel_launch(void* const* d_in, const int* in_sizes, int n_in,
                              void* d_out, int out_size)
{
    const float* C  = (const float*)d_in[0];
    const float* mp = (const float*)d_in[1];
    const float* mt = (const float*)d_in[2];
    float* out = (float*)d_out;

    cudaFuncSetAttribute(sinkhorn_kernel,
                         cudaFuncAttributeMaxDynamicSharedMemorySize, SMEM_BYTES);

    sinkhorn_kernel<<<B_TOT, 512, SMEM_BYTES>>>(C, mp, mt);
    reduce_kernel<<<1, 256>>>(out);
}